// round 1
// baseline (speedup 1.0000x reference)
#include <cuda_runtime.h>

// SpikeFP32LayerNorm: row-wise LayerNorm (no affine), rows of 4096 fp32,
// 8192 rows. One CTA per row; row held in registers (2x float4 per thread),
// single-pass sum/sumsq reduction, normalize from registers.

#define ROWS 8192
#define NCOLS 4096
#define TPB 512            // 16 warps
#define V4_PER_ROW (NCOLS / 4)   // 1024 float4s per row

__global__ __launch_bounds__(TPB, 4)
void spike_ln_kernel(const float* __restrict__ x, float* __restrict__ out) {
    const int row = blockIdx.x;
    const float4* __restrict__ xin =
        reinterpret_cast<const float4*>(x + (size_t)row * NCOLS);
    float4* __restrict__ xout =
        reinterpret_cast<float4*>(out + (size_t)row * NCOLS);

    // Two independent 128-bit loads per thread (coalesced; MLP=2)
    float4 v0 = xin[threadIdx.x];
    float4 v1 = xin[threadIdx.x + TPB];

    float s  = (v0.x + v0.y) + (v0.z + v0.w) + (v1.x + v1.y) + (v1.z + v1.w);
    float sq = v0.x * v0.x + v0.y * v0.y + v0.z * v0.z + v0.w * v0.w
             + v1.x * v1.x + v1.y * v1.y + v1.z * v1.z + v1.w * v1.w;

    // Warp reduction of both accumulators
    #pragma unroll
    for (int off = 16; off > 0; off >>= 1) {
        s  += __shfl_xor_sync(0xFFFFFFFFu, s,  off);
        sq += __shfl_xor_sync(0xFFFFFFFFu, sq, off);
    }

    __shared__ float ssum[16];
    __shared__ float ssq[16];
    __shared__ float s_mean, s_rstd;

    const int wid = threadIdx.x >> 5;
    const int lid = threadIdx.x & 31;
    if (lid == 0) { ssum[wid] = s; ssq[wid] = sq; }
    __syncthreads();

    if (wid == 0) {
        float ts  = (lid < 16) ? ssum[lid] : 0.0f;
        float tsq = (lid < 16) ? ssq[lid]  : 0.0f;
        #pragma unroll
        for (int off = 8; off > 0; off >>= 1) {
            ts  += __shfl_xor_sync(0xFFFFFFFFu, ts,  off);
            tsq += __shfl_xor_sync(0xFFFFFFFFu, tsq, off);
        }
        if (lid == 0) {
            const float inv_n = 1.0f / (float)NCOLS;
            float mean = ts * inv_n;
            float var  = fmaxf(tsq * inv_n - mean * mean, 0.0f);
            float vpe  = var + 1e-6f;
            // rsqrt + one NR step in fp32 (matches FP64 NR-converged rsqrt
            // to ~1 ulp fp32, far inside the 1e-3 rel-err budget)
            float y = rsqrtf(vpe);
            y = 0.5f * y * (3.0f - vpe * (y * y));
            s_mean = mean;
            s_rstd = y;
        }
    }
    __syncthreads();

    const float mean = s_mean;
    const float rstd = s_rstd;

    float4 o0, o1;
    o0.x = (v0.x - mean) * rstd;  o0.y = (v0.y - mean) * rstd;
    o0.z = (v0.z - mean) * rstd;  o0.w = (v0.w - mean) * rstd;
    o1.x = (v1.x - mean) * rstd;  o1.y = (v1.y - mean) * rstd;
    o1.z = (v1.z - mean) * rstd;  o1.w = (v1.w - mean) * rstd;

    xout[threadIdx.x]       = o0;
    xout[threadIdx.x + TPB] = o1;
}

extern "C" void kernel_launch(void* const* d_in, const int* in_sizes, int n_in,
                              void* d_out, int out_size) {
    const float* x = (const float*)d_in[0];
    float* out = (float*)d_out;
    spike_ln_kernel<<<ROWS, TPB>>>(x, out);
}